// round 12
// baseline (speedup 1.0000x reference)
#include <cuda_runtime.h>
#include <cuda_fp16.h>
#include <cstdint>

// out[8192,4096] = x[8192,4096] @ tanh(blocks*mask); blocks = 16 diag blocks 256x256.
// Raw mma.sync.m16n8k16 fp16 path. A is loaded from global straight into the
// per-lane fragment layout (float2 loads), converted fp32->fp16 in registers —
// no smem round-trip for A (cuts smem traffic ~40% and removes the
// cvt->STS->LDSM chain). B: cp.async double-buffered smem + ldmatrix.x4.
// 256 thr, 128x128 tile, 2 CTAs/SM; twin CTAs (nHalf fastest) dedup x in L2.

#define LAYER 4096
#define NROWS 8192
#define NBLK  16
#define BSZ   256
#define KCH   64
#define LDB   72   // fp16 elems (144 B row stride): ldmatrix rows land conflict-free

__device__ __align__(16) __half g_B[NBLK * BSZ * BSZ];  // [blk][n][k]

__device__ __forceinline__ uint32_t smem_u32(const void* p) {
    uint32_t a;
    asm("{ .reg .u64 t; cvta.to.shared.u64 t, %1; cvt.u32.u64 %0, t; }" : "=r"(a) : "l"(p));
    return a;
}
__device__ __forceinline__ uint32_t h2u(__half2 h) {
    return *reinterpret_cast<uint32_t*>(&h);
}

// ---------------- Stage 1: tanh + transpose blocks ----------------
__global__ __launch_bounds__(256) void prep_B(const float* __restrict__ blocks) {
    __shared__ float v[32][BSZ + 1];
    const int kt  = blockIdx.x;   // 0..7
    const int blk = blockIdx.y;   // 0..15
    const int tid = threadIdx.x;

    #pragma unroll
    for (int i = 0; i < 32; i++) {
        int idx = tid + i * 256;
        int k = idx >> 8, n = idx & 255;
        v[k][n] = blocks[(size_t)(blk * BSZ + kt * 32 + k) * LAYER + (size_t)(blk * BSZ + n)];
    }
    __syncthreads();

    const int n = tid;
    uint32_t w[16];
    #pragma unroll
    for (int k2 = 0; k2 < 16; k2++) {
        float t0 = tanhf(v[2 * k2][n]);
        float t1 = tanhf(v[2 * k2 + 1][n]);
        w[k2] = h2u(__floats2half2_rn(t0, t1));
    }
    size_t base = (size_t)(blk * BSZ + n) * BSZ + kt * 32;  // [blk][n][k]
    #pragma unroll
    for (int q = 0; q < 4; q++)
        *reinterpret_cast<uint4*>(&g_B[base + q * 8]) =
            make_uint4(w[4 * q], w[4 * q + 1], w[4 * q + 2], w[4 * q + 3]);
}

// ---------------- Stage 2: mma.sync GEMM ----------------
// dyn smem: sB0 18432 | sB1 18432 = 36864 B  (128 n-rows x LDB halves each)
#define SMB0 0
#define SMB1 18432
#define SM_TOTAL 36864

__device__ __forceinline__ void mma16816(float* d, const uint32_t* a, const uint32_t* b) {
    asm volatile(
        "mma.sync.aligned.m16n8k16.row.col.f32.f16.f16.f32 "
        "{%0,%1,%2,%3}, {%4,%5,%6,%7}, {%8,%9}, {%0,%1,%2,%3};"
        : "+f"(d[0]), "+f"(d[1]), "+f"(d[2]), "+f"(d[3])
        : "r"(a[0]), "r"(a[1]), "r"(a[2]), "r"(a[3]), "r"(b[0]), "r"(b[1]));
}

__global__ void __launch_bounds__(256, 2) bd_mma(const float* __restrict__ x,
                                                 float* __restrict__ out) {
    extern __shared__ __align__(16) char smem[];
    const uint32_t sbase = smem_u32(smem);
    const int tid  = threadIdx.x;
    const int w    = tid >> 5;
    const int lane = tid & 31;
    const int wm   = w >> 1;         // 0..3 -> 32-row band
    const int wn   = w & 1;          // 0..1 -> 64-col band
    const int nHalf = blockIdx.x;    // 0..1  fastest: twin CTAs share x rows in L2
    const int mTile = blockIdx.y;    // 0..63
    const int blk   = blockIdx.z;    // 0..15

    const float*  Asrc = x + (size_t)mTile * 128 * LAYER + (size_t)blk * BSZ;
    const __half* Bsrc = g_B + (size_t)blk * BSZ * BSZ + (size_t)nHalf * 128 * BSZ;

    // A fragment addressing (m16n8k16 row-major A):
    //   lane holds (r, kc), (r+8, kc), (r, kc+8), (r+8, kc+8) with
    //   r = band + frag*16 + (lane>>2), kc = k0 + 2*(lane&3)  (pairs -> float2)
    const int aRow = wm * 32 + (lane >> 2);
    const int kc   = (lane & 3) * 2;
    const float* aPtr[4];
    #pragma unroll
    for (int i = 0; i < 4; i++)
        aPtr[i] = Asrc + (size_t)(aRow + ((i & 1) ? 8 : 0) + ((i >> 1) ? 16 : 0)) * LAYER + kc;
    // aPtr[0]=r, aPtr[1]=r+8 (frag0); aPtr[2]=r+16, aPtr[3]=r+24 (frag1)

    // B ldmatrix lane address pieces (per x4: 4 8x8 matrices covering 2 n-octets x k16)
    const int mi    = lane >> 3;                 // matrix index 0..3
    const int mRow  = lane & 7;
    const int bN    = wn * 64 + ((mi >> 1) ? 8 : 0) + mRow;  // + q*16 per call
    const int bKoff = (mi & 1) ? 8 : 0;                      // + ks*16 per call

    float d[2][8][4];
    #pragma unroll
    for (int mt = 0; mt < 2; mt++)
        #pragma unroll
        for (int o = 0; o < 8; o++)
            #pragma unroll
            for (int e = 0; e < 4; e++) d[mt][o][e] = 0.0f;

    // ---- prologue: B chunk0 -> sB0; A kstep0 -> lp ----
    #pragma unroll
    for (int i = 0; i < 4; i++) {                  // B: 128 rows x 8 uint4 = 1024 ids
        int u = tid + i * 256;
        int n = u >> 3, q = u & 7;
        uint32_t dst = sbase + SMB0 + (uint32_t)(n * LDB + q * 8) * 2;
        const __half* src = Bsrc + (size_t)n * BSZ + q * 8;
        asm volatile("cp.async.ca.shared.global [%0], [%1], 16;" :: "r"(dst), "l"(src) : "memory");
    }
    asm volatile("cp.async.commit_group;" ::: "memory");

    float2 lp[8];
    #pragma unroll
    for (int i = 0; i < 4; i++) {
        lp[2 * i]     = *reinterpret_cast<const float2*>(aPtr[i]);       // k0 + kc
        lp[2 * i + 1] = *reinterpret_cast<const float2*>(aPtr[i] + 8);   // k0 + kc + 8
    }
    asm volatile("cp.async.wait_group 0;" ::: "memory");
    __syncthreads();

    // ---- mainloop: 4 chunks x 4 ksteps; flat kstep t = c*4+ks ----
    #pragma unroll
    for (int c = 0; c < 4; c++) {
        const uint32_t sbB = sbase + ((c & 1) ? SMB1 : SMB0);

        if (c < 3) {   // B(c+1) -> other buffer (last read chunk c-1, sync-separated)
            uint32_t dstB = sbase + (((c + 1) & 1) ? SMB1 : SMB0);
            #pragma unroll
            for (int i = 0; i < 4; i++) {
                int u = tid + i * 256;
                int n = u >> 3, q = u & 7;
                uint32_t dst = dstB + (uint32_t)(n * LDB + q * 8) * 2;
                const __half* src = Bsrc + (size_t)n * BSZ + (c + 1) * KCH + q * 8;
                asm volatile("cp.async.ca.shared.global [%0], [%1], 16;" :: "r"(dst), "l"(src) : "memory");
            }
            asm volatile("cp.async.commit_group;" ::: "memory");
        }

        #pragma unroll
        for (int ks = 0; ks < 4; ks++) {
            const int t = c * 4 + ks;

            // convert prefetched A (kstep t) -> fragments
            uint32_t af[2][4];
            #pragma unroll
            for (int fr = 0; fr < 2; fr++) {
                af[fr][0] = h2u(__floats2half2_rn(lp[4 * fr + 0].x, lp[4 * fr + 0].y)); // (r,kc)
                af[fr][1] = h2u(__floats2half2_rn(lp[4 * fr + 2].x, lp[4 * fr + 2].y)); // (r+8,kc)
                af[fr][2] = h2u(__floats2half2_rn(lp[4 * fr + 1].x, lp[4 * fr + 1].y)); // (r,kc+8)
                af[fr][3] = h2u(__floats2half2_rn(lp[4 * fr + 3].x, lp[4 * fr + 3].y)); // (r+8,kc+8)
            }

            // prefetch A kstep t+1 (global; independent of smem buffers)
            if (t < 15) {
                const int kn = (t + 1) * 16;
                #pragma unroll
                for (int i = 0; i < 4; i++) {
                    lp[2 * i]     = *reinterpret_cast<const float2*>(aPtr[i] + kn);
                    lp[2 * i + 1] = *reinterpret_cast<const float2*>(aPtr[i] + kn + 8);
                }
            }

            // B fragments: 4 x ldmatrix.x4, each = 2 n-octets
            uint32_t bf[8][2];
            #pragma unroll
            for (int q = 0; q < 4; q++) {
                uint32_t addr = sbB + (uint32_t)((bN + q * 16) * LDB + ks * 16 + bKoff) * 2;
                uint32_t r0, r1, r2, r3;
                asm volatile("ldmatrix.sync.aligned.m8n8.x4.shared.b16 {%0,%1,%2,%3}, [%4];"
                             : "=r"(r0), "=r"(r1), "=r"(r2), "=r"(r3) : "r"(addr));
                bf[2 * q][0] = r0; bf[2 * q][1] = r1;       // octet 2q
                bf[2 * q + 1][0] = r2; bf[2 * q + 1][1] = r3; // octet 2q+1
            }

            // 16 MMAs
            #pragma unroll
            for (int o = 0; o < 8; o++) {
                mma16816(d[0][o], af[0], bf[o]);
                mma16816(d[1][o], af[1], bf[o]);
            }
        }

        if (c < 3) {
            asm volatile("cp.async.wait_group 0;" ::: "memory");
            __syncthreads();
        }
    }

    // ---- epilogue: d[mt][o] = 16x8 tile; lane holds (r,2j),(r,2j+1),(r+8,..) ----
    const int colBase = blk * BSZ + nHalf * 128 + wn * 64 + (lane & 3) * 2;
    const int rowBase = mTile * 128 + wm * 32 + (lane >> 2);
    #pragma unroll
    for (int mt = 0; mt < 2; mt++) {
        float* r0 = out + (size_t)(rowBase + mt * 16) * LAYER + colBase;
        float* r1 = r0 + 8 * LAYER;
        #pragma unroll
        for (int o = 0; o < 8; o++) {
            *reinterpret_cast<float2*>(r0 + o * 8) = make_float2(d[mt][o][0], d[mt][o][1]);
            *reinterpret_cast<float2*>(r1 + o * 8) = make_float2(d[mt][o][2], d[mt][o][3]);
        }
    }
}

// ---------------- launch ----------------
extern "C" void kernel_launch(void* const* d_in, const int* in_sizes, int n_in,
                              void* d_out, int out_size) {
    const float* x      = (const float*)d_in[0];
    const float* blocks = (const float*)d_in[1];
    float* out = (float*)d_out;
    (void)in_sizes; (void)n_in; (void)out_size;

    prep_B<<<dim3(8, NBLK), 256>>>(blocks);
    bd_mma<<<dim3(2, NROWS / 128, NBLK), 256, SM_TOTAL>>>(x, out);
}

// round 13
// speedup vs baseline: 1.3735x; 1.3735x over previous
#include <cuda_runtime.h>
#include <cuda_fp16.h>
#include <cstdint>

// out[8192,4096] = x[8192,4096] @ tanh(blocks*mask); blocks = 16 diag blocks 256x256.
// Raw mma.sync.m16n8k16 fp16 path, BOTH operands via ldmatrix.x4 from smem —
// halves the ldmatrix count vs wmma (whose m16n16k16 fragments duplicate loads),
// flipping the kernel from LSU-bound to MMA-bound. Data staging identical to the
// proven round-8 skeleton: A reg-prefetch -> cvt fp32->fp16 -> STS; B cp.async;
// double-buffered; 512 thr; CTA tile 128x256 (full block); grid (64,16).

#define LAYER 4096
#define NROWS 8192
#define NBLK  16
#define BSZ   256
#define KCH   64
#define LDA   72   // fp16 elems; 144 B row stride -> ldmatrix rows hit distinct banks
#define LDB   72

__device__ __align__(16) __half g_B[NBLK * BSZ * BSZ];  // [blk][n][k]

__device__ __forceinline__ uint32_t smem_u32(const void* p) {
    uint32_t a;
    asm("{ .reg .u64 t; cvta.to.shared.u64 t, %1; cvt.u32.u64 %0, t; }" : "=r"(a) : "l"(p));
    return a;
}
__device__ __forceinline__ uint32_t h2u(__half2 h) {
    return *reinterpret_cast<uint32_t*>(&h);
}

// ---------------- Stage 1: tanh + transpose blocks ----------------
__global__ __launch_bounds__(256) void prep_B(const float* __restrict__ blocks) {
    __shared__ float v[32][BSZ + 1];
    const int kt  = blockIdx.x;   // 0..7
    const int blk = blockIdx.y;   // 0..15
    const int tid = threadIdx.x;

    #pragma unroll
    for (int i = 0; i < 32; i++) {
        int idx = tid + i * 256;
        int k = idx >> 8, n = idx & 255;
        v[k][n] = blocks[(size_t)(blk * BSZ + kt * 32 + k) * LAYER + (size_t)(blk * BSZ + n)];
    }
    __syncthreads();

    const int n = tid;
    uint32_t w[16];
    #pragma unroll
    for (int k2 = 0; k2 < 16; k2++) {
        float t0 = tanhf(v[2 * k2][n]);
        float t1 = tanhf(v[2 * k2 + 1][n]);
        w[k2] = h2u(__floats2half2_rn(t0, t1));
    }
    size_t base = (size_t)(blk * BSZ + n) * BSZ + kt * 32;  // [blk][n][k]
    #pragma unroll
    for (int q = 0; q < 4; q++)
        *reinterpret_cast<uint4*>(&g_B[base + q * 8]) =
            make_uint4(w[4 * q], w[4 * q + 1], w[4 * q + 2], w[4 * q + 3]);
}

// ---------------- Stage 2: mma.sync GEMM ----------------
// dyn smem: sA0 18432 | sA1 18432 | sB0 36864 | sB1 36864 = 110592 B
#define SMA0 0
#define SMA1 18432
#define SMB0 36864
#define SMB1 73728
#define SM_TOTAL 110592

__device__ __forceinline__ void mma16816(float* d, const uint32_t* a, const uint32_t* b) {
    asm volatile(
        "mma.sync.aligned.m16n8k16.row.col.f32.f16.f16.f32 "
        "{%0,%1,%2,%3}, {%4,%5,%6,%7}, {%8,%9}, {%0,%1,%2,%3};"
        : "+f"(d[0]), "+f"(d[1]), "+f"(d[2]), "+f"(d[3])
        : "r"(a[0]), "r"(a[1]), "r"(a[2]), "r"(a[3]), "r"(b[0]), "r"(b[1]));
}
__device__ __forceinline__ void ldsm4(uint32_t* r, uint32_t addr) {
    asm volatile("ldmatrix.sync.aligned.m8n8.x4.shared.b16 {%0,%1,%2,%3}, [%4];"
                 : "=r"(r[0]), "=r"(r[1]), "=r"(r[2]), "=r"(r[3]) : "r"(addr));
}

__global__ void __launch_bounds__(512, 1) bd_mma(const float* __restrict__ x,
                                                 float* __restrict__ out) {
    extern __shared__ __align__(16) char smem[];
    const uint32_t sbase = smem_u32(smem);
    const int tid  = threadIdx.x;
    const int w    = tid >> 5;
    const int lane = tid & 31;
    const int wm   = w & 3;          // 0..3 -> 32-row band
    const int wn   = w >> 2;         // 0..3 -> 64-col band
    const int mTile = blockIdx.x;    // 0..63
    const int blk   = blockIdx.y;    // 0..15

    const float*  Asrc = x + (size_t)mTile * 128 * LAYER + (size_t)blk * BSZ;
    const __half* Bsrc = g_B + (size_t)blk * BSZ * BSZ;

    // ldmatrix lane-address components (mi = which 8x8 matrix this lane addresses)
    const int mi    = lane >> 3;
    const int lane7 = lane & 7;
    const int aRowL = (mi & 1) * 8 + lane7;   // row within 16-row frag
    const int aKoff = (mi >> 1) * 8;          // k offset within kstep
    const int bNoff = (mi >> 1) * 8 + lane7;  // n within 16-n group (2 octets)
    const int bKoff = (mi & 1) * 8;

    float d[2][8][4];
    #pragma unroll
    for (int mt = 0; mt < 2; mt++)
        #pragma unroll
        for (int o = 0; o < 8; o++)
            #pragma unroll
            for (int e = 0; e < 4; e++) d[mt][o][e] = 0.0f;

    float4 aReg[4];

    // ---- prologue: A(0) -> regs, B(0) -> sB0 via cp.async ----
    #pragma unroll
    for (int i = 0; i < 4; i++) {                  // A: 128 rows x 16 float4 = 2048 ids
        int f = tid + i * 512;
        int row = f >> 4, c4 = f & 15;
        aReg[i] = *reinterpret_cast<const float4*>(Asrc + (size_t)row * LAYER + c4 * 4);
    }
    #pragma unroll
    for (int i = 0; i < 4; i++) {                  // B: 256 n x 8 uint4 = 2048 ids
        int u = tid + i * 512;
        int n = u >> 3, q = u & 7;
        uint32_t dst = sbase + SMB0 + (uint32_t)(n * LDB + q * 8) * 2;
        const __half* src = Bsrc + (size_t)n * BSZ + q * 8;
        asm volatile("cp.async.ca.shared.global [%0], [%1], 16;" :: "r"(dst), "l"(src) : "memory");
    }
    asm volatile("cp.async.commit_group;" ::: "memory");

    for (int c = 0; c < 4; c++) {
        const int buf = c & 1;
        const uint32_t sA = sbase + (buf ? SMA1 : SMA0);
        const uint32_t sB = sbase + (buf ? SMB1 : SMB0);
        __half* sAp = reinterpret_cast<__half*>(smem + (buf ? SMA1 : SMA0));

        // ---- convert A regs -> sA (fp16) ----
        #pragma unroll
        for (int i = 0; i < 4; i++) {
            int f = tid + i * 512;
            int row = f >> 4, c4 = f & 15;
            __half2 h01 = __floats2half2_rn(aReg[i].x, aReg[i].y);
            __half2 h23 = __floats2half2_rn(aReg[i].z, aReg[i].w);
            *reinterpret_cast<uint2*>(sAp + row * LDA + c4 * 4) = make_uint2(h2u(h01), h2u(h23));
        }

        // ---- prefetch chunk c+1 (A -> regs, B -> other buffer) ----
        if (c < 3) {
            #pragma unroll
            for (int i = 0; i < 4; i++) {
                int f = tid + i * 512;
                int row = f >> 4, c4 = f & 15;
                aReg[i] = *reinterpret_cast<const float4*>(
                    Asrc + (size_t)row * LAYER + (c + 1) * KCH + c4 * 4);
            }
            uint32_t sbB = sbase + (((c + 1) & 1) ? SMB1 : SMB0);
            #pragma unroll
            for (int i = 0; i < 4; i++) {
                int u = tid + i * 512;
                int n = u >> 3, q = u & 7;
                uint32_t dst = sbB + (uint32_t)(n * LDB + q * 8) * 2;
                const __half* src = Bsrc + (size_t)n * BSZ + (c + 1) * KCH + q * 8;
                asm volatile("cp.async.ca.shared.global [%0], [%1], 16;" :: "r"(dst), "l"(src) : "memory");
            }
            asm volatile("cp.async.commit_group;" ::: "memory");
            asm volatile("cp.async.wait_group 1;" ::: "memory");   // chunk c's B done
        } else {
            asm volatile("cp.async.wait_group 0;" ::: "memory");
        }
        __syncthreads();

        // ---- MMA over buf: 4 ksteps ----
        #pragma unroll
        for (int ks = 0; ks < 4; ks++) {
            // A fragments: 2 x ldsm.x4 (rows wm*32 and wm*32+16)
            uint32_t af[2][4];
            ldsm4(af[0], sA + (uint32_t)((wm * 32      + aRowL) * LDA + ks * 16 + aKoff) * 2);
            ldsm4(af[1], sA + (uint32_t)((wm * 32 + 16 + aRowL) * LDA + ks * 16 + aKoff) * 2);
            // B fragments: 4 x ldsm.x4 (each covers 2 n-octets)
            uint32_t bf[8][2];
            #pragma unroll
            for (int q = 0; q < 4; q++) {
                uint32_t r[4];
                ldsm4(r, sB + (uint32_t)((wn * 64 + q * 16 + bNoff) * LDB + ks * 16 + bKoff) * 2);
                bf[2 * q][0] = r[0]; bf[2 * q][1] = r[1];
                bf[2 * q + 1][0] = r[2]; bf[2 * q + 1][1] = r[3];
            }
            // 16 MMAs
            #pragma unroll
            for (int o = 0; o < 8; o++) {
                mma16816(d[0][o], af[0], bf[o]);
                mma16816(d[1][o], af[1], bf[o]);
            }
        }
        __syncthreads();
    }

    // ---- epilogue: lane holds (r,2c),(r,2c+1) / (r+8,..) per octet ----
    const int colBase = blk * BSZ + wn * 64 + (lane & 3) * 2;
    const int rowBase = mTile * 128 + wm * 32 + (lane >> 2);
    #pragma unroll
    for (int mt = 0; mt < 2; mt++) {
        float* r0 = out + (size_t)(rowBase + mt * 16) * LAYER + colBase;
        float* r1 = r0 + 8 * LAYER;
        #pragma unroll
        for (int o = 0; o < 8; o++) {
            *reinterpret_cast<float2*>(r0 + o * 8) = make_float2(d[mt][o][0], d[mt][o][1]);
            *reinterpret_cast<float2*>(r1 + o * 8) = make_float2(d[mt][o][2], d[mt][o][3]);
        }
    }
}

// ---------------- launch ----------------
extern "C" void kernel_launch(void* const* d_in, const int* in_sizes, int n_in,
                              void* d_out, int out_size) {
    const float* x      = (const float*)d_in[0];
    const float* blocks = (const float*)d_in[1];
    float* out = (float*)d_out;
    (void)in_sizes; (void)n_in; (void)out_size;

    cudaFuncSetAttribute(bd_mma, cudaFuncAttributeMaxDynamicSharedMemorySize, SM_TOTAL);

    prep_B<<<dim3(8, NBLK), 256>>>(blocks);
    bd_mma<<<dim3(NROWS / 128, NBLK), 512, SM_TOTAL>>>(x, out);
}